// round 7
// baseline (speedup 1.0000x reference)
#include <cuda_runtime.h>

// LIF membrane recurrence, HBM-bound streaming kernel.
//   mem[t] = 0.25 * mem[t-1] * (1 - spike[t-1]) + x[t] ; spike[t] = mem[t] > 0.5
// x: (8, 32, 128, 32, 32) fp32. 134 MB read + 134 MB write, zero reuse.
//
// History (kernel time, ncu):
//   R0/R3 baseline (256 thr, float4, front-batch 8): 36.1us, DRAM 75%. BEST.
//   R1 (.cs ld+st)   -> 44.7us : forces write stream to DRAM in-kernel. NO.
//   R2 (.cg loads)   -> 45.3us : L1 bypass hurts vectorized stream. NO.
//   R4 (sw pipeline) -> 38.1us : de-batching loads adds issue overhead. NO.
//   R5 (tile x2)     -> 37.2us : neutral; occupancy halved, DRAM flat. NO.
// R6: final axis — R0 shape with block=512 (fewer CTAs, same per-thread
// shape, regs stay 32). If neutral, R0 is the committed floor.

#define T_STEPS 8
#define INNER   (32 * 128 * 32 * 32)   // 4,194,304 elements per timestep
#define INNER4  (INNER / 4)            // 1,048,576 float4 sites

__global__ void lif_kernel(const float4* __restrict__ x, float4* __restrict__ out) {
    int i = blockIdx.x * blockDim.x + threadIdx.x;
    if (i >= INNER4) return;

    // Front-batch all 8 timestep loads (independent -> MLP=8).
    float4 xv[T_STEPS];
#pragma unroll
    for (int t = 0; t < T_STEPS; ++t) {
        xv[t] = x[(size_t)t * INNER4 + i];
    }

    const float DECAY = 0.25f;
    const float THR   = 0.5f;

    float m0 = 0.f, m1 = 0.f, m2 = 0.f, m3 = 0.f;
    float s0 = 0.f, s1 = 0.f, s2 = 0.f, s3 = 0.f;

#pragma unroll
    for (int t = 0; t < T_STEPS; ++t) {
        m0 = DECAY * m0 * (1.0f - s0) + xv[t].x;
        m1 = DECAY * m1 * (1.0f - s1) + xv[t].y;
        m2 = DECAY * m2 * (1.0f - s2) + xv[t].z;
        m3 = DECAY * m3 * (1.0f - s3) + xv[t].w;
        s0 = (m0 > THR) ? 1.0f : 0.0f;
        s1 = (m1 > THR) ? 1.0f : 0.0f;
        s2 = (m2 > THR) ? 1.0f : 0.0f;
        s3 = (m3 > THR) ? 1.0f : 0.0f;
        out[(size_t)t * INNER4 + i] = make_float4(s0, s1, s2, s3);
    }
}

extern "C" void kernel_launch(void* const* d_in, const int* in_sizes, int n_in,
                              void* d_out, int out_size) {
    const float4* x = (const float4*)d_in[0];
    float4* out = (float4*)d_out;
    int threads = 512;
    int blocks = (INNER4 + threads - 1) / threads;   // 2048
    lif_kernel<<<blocks, threads>>>(x, out);
}

// round 8
// speedup vs baseline: 1.0021x; 1.0021x over previous
#include <cuda_runtime.h>

// LIF membrane recurrence — FINAL.
//   mem[0] = x[0]; mem[t] = 0.25 * mem[t-1] * (1 - spike[t-1]) + x[t]
//   spike[t] = (mem[t] > 0.5)
// x: (8, 32, 128, 32, 32) fp32. Recurrence only along t; 4,194,304 independent
// sites. 134 MB read + 134 MB write, zero reuse -> pure HBM-bound.
//
// Session conclusion: this shape is at the DRAM mixed-stream floor.
//   R0/R3/R6 (plain float4, front-batch 8 loads): 36.1us kernel, DRAM 75%,
//     effective ~7.4 TB/s counting deferred L2 writeback. BEST.
//   R1 (.cs ld+st)   44.7us  — evicting the write stream early kills it.
//   R2 (.cg loads)   45.3us  — L1 bypass hurts vectorized streaming.
//   R4 (sw pipeline) 38.1us  — de-batching loads adds issue overhead.
//   R5 (tile x2)     37.2us  — neutral; DRAM flat.
//   R6 (block 512)   36.1us  — neutral.
// Compute pipes <9%, issue 15%, tensor 0%: no non-memory lever exists.

#define T_STEPS 8
#define INNER   (32 * 128 * 32 * 32)   // 4,194,304 elements per timestep
#define INNER4  (INNER / 4)            // 1,048,576 float4 sites

__global__ void lif_kernel(const float4* __restrict__ x, float4* __restrict__ out) {
    int i = blockIdx.x * blockDim.x + threadIdx.x;
    if (i >= INNER4) return;

    // Front-batch all 8 timestep loads (independent -> MLP=8).
    float4 xv[T_STEPS];
#pragma unroll
    for (int t = 0; t < T_STEPS; ++t) {
        xv[t] = x[(size_t)t * INNER4 + i];
    }

    const float DECAY = 0.25f;
    const float THR   = 0.5f;

    float m0 = 0.f, m1 = 0.f, m2 = 0.f, m3 = 0.f;
    float s0 = 0.f, s1 = 0.f, s2 = 0.f, s3 = 0.f;

#pragma unroll
    for (int t = 0; t < T_STEPS; ++t) {
        m0 = DECAY * m0 * (1.0f - s0) + xv[t].x;
        m1 = DECAY * m1 * (1.0f - s1) + xv[t].y;
        m2 = DECAY * m2 * (1.0f - s2) + xv[t].z;
        m3 = DECAY * m3 * (1.0f - s3) + xv[t].w;
        s0 = (m0 > THR) ? 1.0f : 0.0f;
        s1 = (m1 > THR) ? 1.0f : 0.0f;
        s2 = (m2 > THR) ? 1.0f : 0.0f;
        s3 = (m3 > THR) ? 1.0f : 0.0f;
        out[(size_t)t * INNER4 + i] = make_float4(s0, s1, s2, s3);
    }
}

extern "C" void kernel_launch(void* const* d_in, const int* in_sizes, int n_in,
                              void* d_out, int out_size) {
    const float4* x = (const float4*)d_in[0];
    float4* out = (float4*)d_out;
    int threads = 256;
    int blocks = (INNER4 + threads - 1) / threads;   // 4096
    lif_kernel<<<blocks, threads>>>(x, out);
}